// round 11
// baseline (speedup 1.0000x reference)
#include <cuda_runtime.h>
#include <cuda_bf16.h>
#include <cstdint>

#define Bn  16
#define Tn  2048
#define Cn  384
#define DKn 64

// Q: row-major pre-split bf16 (read directly as LDG fragments)
__device__ __align__(16) __nv_bfloat16 g_qhi [Bn * Tn * DKn];
__device__ __align__(16) __nv_bfloat16 g_qlo [Bn * Tn * DKn];
// K / Vt: pre-SWIZZLED 8KB tile blocks [b][tile16=32][64 rows][128B]
__device__ __align__(128) unsigned char g_khi_sw[Bn * 32 * 8192];
__device__ __align__(128) unsigned char g_klo_sw[Bn * 32 * 8192];
__device__ __align__(128) unsigned char g_vhi_sw[Bn * 32 * 8192];
__device__ __align__(128) unsigned char g_vlo_sw[Bn * 32 * 8192];
// W: pre-SWIZZLED 24KB chunk blocks [chunk6][192 rows][128B]
__device__ __align__(128) unsigned char g_wthi_sw[6 * 24576];
__device__ __align__(128) unsigned char g_wtlo_sw[6 * 24576];

// ===================== helpers =====================
__device__ __forceinline__ uint32_t smem_u32(const void* p) {
    uint32_t a;
    asm("{ .reg .u64 t; cvta.to.shared.u64 t, %1; cvt.u32.u64 %0, t; }" : "=r"(a) : "l"(p));
    return a;
}
__device__ __forceinline__ uint32_t pack2(float e0, float e1) {
    uint32_t r;
    asm("cvt.rn.bf16x2.f32 %0, %1, %2;" : "=r"(r) : "f"(e1), "f"(e0));
    return r;
}
__device__ __forceinline__ void split2(float e0, float e1, uint32_t& hi, uint32_t& lo) {
    hi = pack2(e0, e1);
    float h0 = __uint_as_float(hi << 16);
    float h1 = __uint_as_float(hi & 0xffff0000u);
    lo = pack2(e0 - h0, e1 - h1);
}
__device__ __forceinline__ void ldsm4(uint32_t r[4], uint32_t addr) {
    asm volatile("ldmatrix.sync.aligned.m8n8.x4.shared.b16 {%0,%1,%2,%3}, [%4];"
        : "=r"(r[0]), "=r"(r[1]), "=r"(r[2]), "=r"(r[3]) : "r"(addr));
}
__device__ __forceinline__ void mma16816(float c[4], const uint32_t a[4],
                                         uint32_t b0, uint32_t b1) {
    asm volatile(
        "mma.sync.aligned.m16n8k16.row.col.f32.bf16.bf16.f32 "
        "{%0,%1,%2,%3},{%4,%5,%6,%7},{%8,%9},{%0,%1,%2,%3};"
        : "+f"(c[0]), "+f"(c[1]), "+f"(c[2]), "+f"(c[3])
        : "r"(a[0]), "r"(a[1]), "r"(a[2]), "r"(a[3]), "r"(b0), "r"(b1));
}
#define MBAR_INIT(a, cnt) \
    asm volatile("mbarrier.init.shared.b64 [%0], %1;" :: "r"(a), "r"(cnt) : "memory")
#define MBAR_EXPECT(a, bytes) \
    asm volatile("mbarrier.arrive.expect_tx.shared.b64 _, [%0], %1;" :: "r"(a), "r"(bytes) : "memory")
#define BULK_G2S(dst, src, sz, mbar) \
    asm volatile("cp.async.bulk.shared::cta.global.mbarrier::complete_tx::bytes [%0], [%1], %2, [%3];" \
        :: "r"(dst), "l"(src), "r"(sz), "r"(mbar) : "memory")
#define FENCE_PROXY() asm volatile("fence.proxy.async.shared::cta;" ::: "memory")
#define MBARRIER_WAIT(a, ph) do {                                            \
    uint32_t _m = (a), _p = (ph), _d;                                        \
    asm volatile("{ .reg .pred p; mbarrier.try_wait.parity.acquire.cta.shared::cta.b64 p, [%1], %2; selp.b32 %0,1,0,p; }" \
        : "=r"(_d) : "r"(_m), "r"(_p) : "memory");                           \
    if (!_d) {                                                               \
        asm volatile("{ .reg .pred P1; WL_%=: mbarrier.try_wait.parity.acquire.cta.shared::cta.b64 P1, [%0], %1, 0x989680; @P1 bra.uni WD_%=; bra.uni WL_%=; WD_%=: }" \
            :: "r"(_m), "r"(_p) : "memory");                                 \
    } } while (0)

extern __shared__ __align__(16) char dsmem[];

// ===================== prep_w: transpose + split + swizzle W once ===========
__global__ __launch_bounds__(256) void prep_w(
    const float* __restrict__ WQ,
    const float* __restrict__ WK,
    const float* __restrict__ WV)
{
    __shared__ float sw[64][65];
    const int tid = threadIdx.x;
    const int m   = blockIdx.x / 6;
    const int kc  = blockIdx.x % 6;
    const int kk  = kc * 64;
    const float* W = (m == 0) ? WQ : ((m == 1) ? WK : WV);

#pragma unroll
    for (int it = 0; it < 4; it++) {
        int idx = tid + (it << 8);
        int k = idx >> 4, n4 = (idx & 15) << 2;
        float4 v = *(const float4*)(W + (size_t)(kk + k) * DKn + n4);
        sw[k][n4] = v.x; sw[k][n4 + 1] = v.y; sw[k][n4 + 2] = v.z; sw[k][n4 + 3] = v.w;
    }
    __syncthreads();

#pragma unroll
    for (int it = 0; it < 2; it++) {
        int idx = tid + (it << 8);
        int n = idx >> 3, k0 = (idx & 7) << 3;
        uint32_t h[4], lo[4];
#pragma unroll
        for (int j = 0; j < 4; j++)
            split2(sw[k0 + 2 * j][n], sw[k0 + 2 * j + 1][n], h[j], lo[j]);
        int gn = m * 64 + n;
        uint32_t addr = (uint32_t)kc * 24576u + (uint32_t)gn * 128u
                      + (uint32_t)((((k0 >> 3) ^ (gn & 7)) << 4));
        *(uint4*)(g_wthi_sw + addr) = make_uint4(h[0], h[1], h[2], h[3]);
        *(uint4*)(g_wtlo_sw + addr) = make_uint4(lo[0], lo[1], lo[2], lo[3]);
    }
}

// ===================== projection: bulk-copy staging ========================
#define P_X0 0u
#define P_XSTRIDE 36864u
#define P_WT0 73728u
#define P_WSTRIDE 49152u
#define P_MBAR 172032u
#define PROJ_SMEM (172032u + 192u)

__global__ __launch_bounds__(256, 1) void proj_tc_kernel(const float* __restrict__ x)
{
    uint32_t raw = smem_u32(dsmem);
    uint32_t sb  = (raw + 127u) & ~127u;
    char*    bp  = dsmem + (sb - raw);
    float (*vt)[65] = (float(*)[65])(bp + P_WT0);   // epilogue overlay

    const int tid = threadIdx.x;
    const int w   = tid >> 5;
    const int l   = tid & 31;
    const int r0  = blockIdx.x * 128;

    float acc[24][4];
#pragma unroll
    for (int i = 0; i < 24; i++)
#pragma unroll
        for (int j = 0; j < 4; j++) acc[i][j] = 0.f;

    const int brow = l & 7;
    const int bu   = l >> 3;
    const int ra   = (w << 4) + (l >> 2);

    if (tid == 0) {
        MBAR_INIT(sb + P_MBAR, 130);
        MBAR_INIT(sb + P_MBAR + 8, 130);
    }
    FENCE_PROXY();
    __syncthreads();

    {
        uint32_t mb = sb + P_MBAR;
        if (tid < 128) {
            MBAR_EXPECT(mb, 256u);
            BULK_G2S(sb + P_X0 + (uint32_t)tid * 288u,
                     x + (size_t)(r0 + tid) * Cn, 256u, mb);
        } else if (tid < 130) {
            MBAR_EXPECT(mb, 24576u);
            const unsigned char* src = (tid == 128) ? g_wthi_sw : g_wtlo_sw;
            BULK_G2S(sb + P_WT0 + (uint32_t)(tid - 128) * 24576u, src, 24576u, mb);
        }
    }

    for (int c = 0; c < Cn / 64; c++) {
        MBARRIER_WAIT(sb + P_MBAR + (uint32_t)((c & 1) << 3), (c >> 1) & 1);
        __syncthreads();
        if (c + 1 < Cn / 64) {
            uint32_t slot = (uint32_t)((c + 1) & 1);
            uint32_t mb = sb + P_MBAR + (slot << 3);
            if (tid < 128) {
                MBAR_EXPECT(mb, 256u);
                BULK_G2S(sb + P_X0 + slot * P_XSTRIDE + (uint32_t)tid * 288u,
                         x + (size_t)(r0 + tid) * Cn + (c + 1) * 64, 256u, mb);
            } else if (tid < 130) {
                MBAR_EXPECT(mb, 24576u);
                const unsigned char* src =
                    ((tid == 128) ? g_wthi_sw : g_wtlo_sw) + (size_t)(c + 1) * 24576u;
                BULK_G2S(sb + P_WT0 + slot * P_WSTRIDE + (uint32_t)(tid - 128) * 24576u,
                         src, 24576u, mb);
            }
        }

        const char*    xb  = bp + P_X0 + (uint32_t)(c & 1) * P_XSTRIDE;
        const uint32_t wtb = sb + P_WT0 + (uint32_t)(c & 1) * P_WSTRIDE;

        uint32_t ah[4][4], al[4][4];
        {
            const char* rowa = xb + (uint32_t)ra * 288u;
            const char* rowb = rowa + 8u * 288u;
#pragma unroll
            for (int ks = 0; ks < 4; ks++) {
                int c0 = (ks << 6) + ((l & 3) << 3);
                float2 p0 = *(const float2*)(rowa + c0);
                float2 p1 = *(const float2*)(rowb + c0);
                float2 p2 = *(const float2*)(rowa + c0 + 32);
                float2 p3 = *(const float2*)(rowb + c0 + 32);
                split2(p0.x, p0.y, ah[ks][0], al[ks][0]);
                split2(p1.x, p1.y, ah[ks][1], al[ks][1]);
                split2(p2.x, p2.y, ah[ks][2], al[ks][2]);
                split2(p3.x, p3.y, ah[ks][3], al[ks][3]);
            }
        }
#pragma unroll
        for (int nt = 0; nt < 24; nt++) {
            int rowb = (nt << 3) + brow;
            uint32_t rb = wtb + (uint32_t)rowb * 128u;
            uint32_t s0 = (uint32_t)((bu       ^ (rowb & 7)) << 4);
            uint32_t s1 = (uint32_t)(((4 + bu) ^ (rowb & 7)) << 4);
            uint32_t bh[8], bl[8];
            ldsm4(bh,     rb + s0);
            ldsm4(bh + 4, rb + s1);
            ldsm4(bl,     rb + 24576u + s0);
            ldsm4(bl + 4, rb + 24576u + s1);
#pragma unroll
            for (int s = 0; s < 4; s++) {
                mma16816(acc[nt], ah[s], bh[2 * s], bh[2 * s + 1]);
                mma16816(acc[nt], ah[s], bl[2 * s], bl[2 * s + 1]);
                mma16816(acc[nt], al[s], bh[2 * s], bh[2 * s + 1]);
            }
        }
        __syncthreads();
    }

    // ---- epilogue ----
    const int rl = (w << 4) + (l >> 2);
    const int cc = (l & 3) << 1;
    const int b  = r0 >> 11;
    const int t0 = r0 & 2047;
#pragma unroll
    for (int nt = 0; nt < 8; nt++) {
        int cidx = (nt << 3) + cc;
        uint32_t h, lo;
        size_t row0 = (size_t)(r0 + rl);
        split2(acc[nt][0] * 0.125f, acc[nt][1] * 0.125f, h, lo);
        *(uint32_t*)(g_qhi + row0 * 64 + cidx) = h;
        *(uint32_t*)(g_qlo + row0 * 64 + cidx) = lo;
        split2(acc[nt][2] * 0.125f, acc[nt][3] * 0.125f, h, lo);
        *(uint32_t*)(g_qhi + (row0 + 8) * 64 + cidx) = h;
        *(uint32_t*)(g_qlo + (row0 + 8) * 64 + cidx) = lo;

        {
            int t = t0 + rl;
            int rt = t & 63;
            uint32_t ka = ((uint32_t)(b * 32 + (t >> 6)) << 13)
                        + (uint32_t)rt * 128u
                        + (uint32_t)((nt ^ (rt & 7)) << 4) + (uint32_t)(cc << 1);
            split2(acc[nt + 8][0], acc[nt + 8][1], h, lo);
            *(uint32_t*)(g_khi_sw + ka) = h;
            *(uint32_t*)(g_klo_sw + ka) = lo;
            int t2 = t + 8;
            int rt2 = t2 & 63;
            uint32_t ka2 = ((uint32_t)(b * 32 + (t2 >> 6)) << 13)
                         + (uint32_t)rt2 * 128u
                         + (uint32_t)((nt ^ (rt2 & 7)) << 4) + (uint32_t)(cc << 1);
            split2(acc[nt + 8][2], acc[nt + 8][3], h, lo);
            *(uint32_t*)(g_khi_sw + ka2) = h;
            *(uint32_t*)(g_klo_sw + ka2) = lo;
        }

        vt[rl][cidx]         = acc[nt + 16][0];
        vt[rl][cidx + 1]     = acc[nt + 16][1];
        vt[rl + 8][cidx]     = acc[nt + 16][2];
        vt[rl + 8][cidx + 1] = acc[nt + 16][3];
    }
    __syncthreads();

    {
        const int d  = tid >> 2;
        const int tq = (tid & 3) << 5;
#pragma unroll
        for (int g = 0; g < 8; g++) {
            int tl = tq + g * 4;
            float v0 = vt[tl][d], v1 = vt[tl + 1][d];
            float v2 = vt[tl + 2][d], v3 = vt[tl + 3][d];
            uint32_t h0, h1, l0, l1;
            split2(v0, v1, h0, l0);
            split2(v2, v3, h1, l1);
            int t = t0 + tl;
            int tin = t & 63;
            uint32_t va = ((uint32_t)(b * 32 + (t >> 6)) << 13)
                        + (uint32_t)d * 128u
                        + (uint32_t)(((tin >> 3) ^ (d & 7)) << 4)
                        + (uint32_t)((tin & 7) << 1);
            *(uint2*)(g_vhi_sw + va) = make_uint2(h0, h1);
            *(uint2*)(g_vlo_sw + va) = make_uint2(l0, l1);
        }
    }
}

// ===================== attention: double-buffered bulk, 3 CTAs/SM ===========
// smem: 2 KV buffers @0, each 32KB: KHI +0, KLO +8192, VHI +16384, VLO +24576;
//       2 mbarriers @65536.
#define A_KHI 0u
#define A_KLO 8192u
#define A_VHI 16384u
#define A_VLO 24576u
#define A_MBAR 65536u
#define ATTN_SMEM (65536u + 192u)

__device__ __forceinline__ void issue_kv_bulk(uint32_t dst, uint32_t mb, int b, int tile) {
    size_t off = (size_t)(b * 32 + tile) << 13;
    MBAR_EXPECT(mb, 32768u);
    BULK_G2S(dst + A_KHI, g_khi_sw + off, 8192u, mb);
    BULK_G2S(dst + A_KLO, g_klo_sw + off, 8192u, mb);
    BULK_G2S(dst + A_VHI, g_vhi_sw + off, 8192u, mb);
    BULK_G2S(dst + A_VLO, g_vlo_sw + off, 8192u, mb);
}

__global__ __launch_bounds__(128, 3) void attn_kernel(float* __restrict__ out)
{
    uint32_t raw = smem_u32(dsmem);
    uint32_t sb  = (raw + 127u) & ~127u;

    const int tid = threadIdx.x;
    const int w   = tid >> 5;
    const int l   = tid & 31;

    const int bx = blockIdx.x;
    const int qt = 31 - (bx >> 4);          // heavy q-tiles first
    const int b  = bx & 15;
    const int q0 = qt << 6;
    const int ntiles = qt + 1;

    if (tid == 0) {
        MBAR_INIT(sb + A_MBAR, 1);
        MBAR_INIT(sb + A_MBAR + 8, 1);
    }
    FENCE_PROXY();
    __syncthreads();
    if (tid == 0) issue_kv_bulk(sb, sb + A_MBAR, b, 0);

    // ---- Q hi fragments from global (resident whole loop) ----
    const int rowa = q0 + (w << 4) + (l >> 2);
    const int cb   = (l & 3) << 1;
    const __nv_bfloat16* phq = g_qhi + (((size_t)(b * Tn + rowa)) << 6) + cb;
    const __nv_bfloat16* plq = g_qlo + (((size_t)(b * Tn + rowa)) << 6) + cb;
    uint32_t qh[4][4];
#pragma unroll
    for (int ks = 0; ks < 4; ks++) {
        int c0 = ks << 4;
        qh[ks][0] = *(const uint32_t*)(phq + c0);
        qh[ks][1] = *(const uint32_t*)(phq + 512 + c0);
        qh[ks][2] = *(const uint32_t*)(phq + c0 + 8);
        qh[ks][3] = *(const uint32_t*)(phq + 512 + c0 + 8);
    }

    float m0 = -3.0e38f, m1 = -3.0e38f, ls0 = 0.f, ls1 = 0.f;
    float o[8][4];
#pragma unroll
    for (int i = 0; i < 8; i++)
#pragma unroll
        for (int j = 0; j < 4; j++) o[i][j] = 0.f;

    const int wrow0 = q0 + (w << 4);
    const int brow  = l & 7;
    const int bu    = l >> 3;

    for (int it = 0; it < ntiles; it++) {
        const int ks = it << 6;
        const int cslot = it & 1;
        MBARRIER_WAIT(sb + A_MBAR + (uint32_t)(cslot << 3), (it >> 1) & 1);
        __syncthreads();                      // also certifies slot^1 is free
        if (tid == 0 && it + 1 < ntiles) {
            int pslot = cslot ^ 1;
            issue_kv_bulk(sb + (uint32_t)pslot * 32768u,
                          sb + A_MBAR + (uint32_t)(pslot << 3), b, it + 1);
        }
        const uint32_t kvb = sb + (uint32_t)cslot * 32768u;

        if (ks <= wrow0 + 15) {
            // ---- q-lo fragments: reload per tile (L1-resident) ----
            uint32_t ql[4][4];
#pragma unroll
            for (int s = 0; s < 4; s++) {
                int c0 = s << 4;
                ql[s][0] = *(const uint32_t*)(plq + c0);
                ql[s][1] = *(const uint32_t*)(plq + 512 + c0);
                ql[s][2] = *(const uint32_t*)(plq + c0 + 8);
                ql[s][3] = *(const uint32_t*)(plq + 512 + c0 + 8);
            }

            float sc[8][4];
#pragma unroll
            for (int nt = 0; nt < 8; nt++) {
                int row = (nt << 3) + brow;
                uint32_t rb = kvb + (uint32_t)row * 128u;
                uint32_t s0 = (uint32_t)((bu       ^ (row & 7)) << 4);
                uint32_t s1 = (uint32_t)(((4 + bu) ^ (row & 7)) << 4);
                uint32_t kh8[8], kl8[8];
                ldsm4(kh8,     rb + A_KHI + s0);
                ldsm4(kh8 + 4, rb + A_KHI + s1);
                ldsm4(kl8,     rb + A_KLO + s0);
                ldsm4(kl8 + 4, rb + A_KLO + s1);
#pragma unroll
                for (int j = 0; j < 4; j++) sc[nt][j] = 0.f;
#pragma unroll
                for (int s = 0; s < 4; s++) {
                    mma16816(sc[nt], qh[s], kh8[2 * s], kh8[2 * s + 1]);
                    mma16816(sc[nt], qh[s], kl8[2 * s], kl8[2 * s + 1]);
                    mma16816(sc[nt], ql[s], kh8[2 * s], kh8[2 * s + 1]);
                }
            }

            const int R0 = wrow0 + (l >> 2);
            if (ks + 64 > wrow0) {
                int colb = ks + ((l & 3) << 1);
#pragma unroll
                for (int nt = 0; nt < 8; nt++) {
                    int c0 = colb + (nt << 3);
                    if (c0     > R0)     sc[nt][0] = -3.0e38f;
                    if (c0 + 1 > R0)     sc[nt][1] = -3.0e38f;
                    if (c0     > R0 + 8) sc[nt][2] = -3.0e38f;
                    if (c0 + 1 > R0 + 8) sc[nt][3] = -3.0e38f;
                }
            }

            float tm0 = -3.0e38f, tm1 = -3.0e38f;
#pragma unroll
            for (int nt = 0; nt < 8; nt++) {
                tm0 = fmaxf(tm0, fmaxf(sc[nt][0], sc[nt][1]));
                tm1 = fmaxf(tm1, fmaxf(sc[nt][2], sc[nt][3]));
            }
            tm0 = fmaxf(tm0, __shfl_xor_sync(0xffffffffu, tm0, 1));
            tm0 = fmaxf(tm0, __shfl_xor_sync(0xffffffffu, tm0, 2));
            tm1 = fmaxf(tm1, __shfl_xor_sync(0xffffffffu, tm1, 1));
            tm1 = fmaxf(tm1, __shfl_xor_sync(0xffffffffu, tm1, 2));
            float mn0 = fmaxf(m0, tm0), mn1 = fmaxf(m1, tm1);
            float c0 = __expf(m0 - mn0), c1 = __expf(m1 - mn1);

            float ps0 = 0.f, ps1 = 0.f;
            uint32_t phi[4][4], plo[4][4];
#pragma unroll
            for (int s = 0; s < 4; s++) {
#pragma unroll
                for (int h = 0; h < 2; h++) {
                    int nt = 2 * s + h;
                    float p0 = __expf(sc[nt][0] - mn0);
                    float p1 = __expf(sc[nt][1] - mn0);
                    float p2 = __expf(sc[nt][2] - mn1);
                    float p3 = __expf(sc[nt][3] - mn1);
                    ps0 += p0 + p1;
                    ps1 += p2 + p3;
                    split2(p0, p1, phi[s][2 * h],     plo[s][2 * h]);
                    split2(p2, p3, phi[s][2 * h + 1], plo[s][2 * h + 1]);
                }
            }
            ps0 += __shfl_xor_sync(0xffffffffu, ps0, 1);
            ps0 += __shfl_xor_sync(0xffffffffu, ps0, 2);
            ps1 += __shfl_xor_sync(0xffffffffu, ps1, 1);
            ps1 += __shfl_xor_sync(0xffffffffu, ps1, 2);
            ls0 = ls0 * c0 + ps0;
            ls1 = ls1 * c1 + ps1;
            m0 = mn0; m1 = mn1;

#pragma unroll
            for (int nt = 0; nt < 8; nt++) {
                o[nt][0] *= c0; o[nt][1] *= c0;
                o[nt][2] *= c1; o[nt][3] *= c1;
            }
#pragma unroll
            for (int nt = 0; nt < 8; nt++) {
                int row = (nt << 3) + brow;
                uint32_t rb = kvb + (uint32_t)row * 128u;
                uint32_t s0 = (uint32_t)((bu       ^ (row & 7)) << 4);
                uint32_t s1 = (uint32_t)(((4 + bu) ^ (row & 7)) << 4);
                uint32_t vh8[8], vl8[8];
                ldsm4(vh8,     rb + A_VHI + s0);
                ldsm4(vh8 + 4, rb + A_VHI + s1);
                ldsm4(vl8,     rb + A_VLO + s0);
                ldsm4(vl8 + 4, rb + A_VLO + s1);
#pragma unroll
                for (int s = 0; s < 4; s++) {
                    mma16816(o[nt], phi[s], vh8[2 * s], vh8[2 * s + 1]);
                    mma16816(o[nt], phi[s], vl8[2 * s], vl8[2 * s + 1]);
                    mma16816(o[nt], plo[s], vh8[2 * s], vh8[2 * s + 1]);
                }
            }
        }
    }

    const float inv0 = 1.f / ls0, inv1 = 1.f / ls1;
    const int R0g = q0 + (w << 4) + (l >> 2);
    float* o0p = out + (((size_t)(b * Tn + R0g)) << 6) + ((l & 3) << 1);
    float* o1p = o0p + (8 << 6);
#pragma unroll
    for (int nt = 0; nt < 8; nt++) {
        *(float2*)(o0p + (nt << 3)) = make_float2(o[nt][0] * inv0, o[nt][1] * inv0);
        *(float2*)(o1p + (nt << 3)) = make_float2(o[nt][2] * inv1, o[nt][3] * inv1);
    }
}

// ===================== launch =====================
extern "C" void kernel_launch(void* const* d_in, const int* in_sizes, int n_in,
                              void* d_out, int out_size)
{
    const float* x  = (const float*)d_in[0];
    const float* WQ = (const float*)d_in[1];
    const float* WK = (const float*)d_in[2];
    const float* WV = (const float*)d_in[3];
    float* out = (float*)d_out;

    cudaFuncSetAttribute(proj_tc_kernel,
                         cudaFuncAttributeMaxDynamicSharedMemorySize, PROJ_SMEM);
    cudaFuncSetAttribute(attn_kernel,
                         cudaFuncAttributeMaxDynamicSharedMemorySize, ATTN_SMEM);

    prep_w<<<18, 256>>>(WQ, WK, WV);
    proj_tc_kernel<<<256, 256, PROJ_SMEM>>>(x);
    attn_kernel<<<512, 128, ATTN_SMEM>>>(out);
}

// round 12
// speedup vs baseline: 1.2626x; 1.2626x over previous
#include <cuda_runtime.h>
#include <cuda_bf16.h>
#include <cstdint>

#define Bn  16
#define Tn  2048
#define Cn  384
#define DKn 64

// Pre-split bf16 operands
__device__ __align__(16) __nv_bfloat16 g_qhi [Bn * Tn * DKn];
__device__ __align__(16) __nv_bfloat16 g_qlo [Bn * Tn * DKn];
__device__ __align__(16) __nv_bfloat16 g_khi [Bn * Tn * DKn];
__device__ __align__(16) __nv_bfloat16 g_klo [Bn * Tn * DKn];
__device__ __align__(16) __nv_bfloat16 g_vthi[Bn * DKn * Tn];   // [b][d][t]
__device__ __align__(16) __nv_bfloat16 g_vtlo[Bn * DKn * Tn];
// Pre-transposed, pre-split weights: [n][k] with n in 0..191 = [Q|K|V]
__device__ __align__(16) __nv_bfloat16 g_wthi[192 * Cn];
__device__ __align__(16) __nv_bfloat16 g_wtlo[192 * Cn];

// ===================== helpers =====================
__device__ __forceinline__ uint32_t smem_u32(const void* p) {
    uint32_t a;
    asm("{ .reg .u64 t; cvta.to.shared.u64 t, %1; cvt.u32.u64 %0, t; }" : "=r"(a) : "l"(p));
    return a;
}
__device__ __forceinline__ uint32_t pack2(float e0, float e1) {
    uint32_t r;
    asm("cvt.rn.bf16x2.f32 %0, %1, %2;" : "=r"(r) : "f"(e1), "f"(e0));
    return r;
}
__device__ __forceinline__ void split2(float e0, float e1, uint32_t& hi, uint32_t& lo) {
    hi = pack2(e0, e1);
    float h0 = __uint_as_float(hi << 16);
    float h1 = __uint_as_float(hi & 0xffff0000u);
    lo = pack2(e0 - h0, e1 - h1);
}
__device__ __forceinline__ float ex2f(float x) {
    float r;
    asm("ex2.approx.f32 %0, %1;" : "=f"(r) : "f"(x));
    return r;
}
__device__ __forceinline__ void ldsm4(uint32_t r[4], uint32_t addr) {
    asm volatile("ldmatrix.sync.aligned.m8n8.x4.shared.b16 {%0,%1,%2,%3}, [%4];"
        : "=r"(r[0]), "=r"(r[1]), "=r"(r[2]), "=r"(r[3]) : "r"(addr));
}
__device__ __forceinline__ void mma16816(float c[4], const uint32_t a[4],
                                         uint32_t b0, uint32_t b1) {
    asm volatile(
        "mma.sync.aligned.m16n8k16.row.col.f32.bf16.bf16.f32 "
        "{%0,%1,%2,%3},{%4,%5,%6,%7},{%8,%9},{%0,%1,%2,%3};"
        : "+f"(c[0]), "+f"(c[1]), "+f"(c[2]), "+f"(c[3])
        : "r"(a[0]), "r"(a[1]), "r"(a[2]), "r"(a[3]), "r"(b0), "r"(b1));
}
#define STS128(a, v) \
    asm volatile("st.shared.v4.b32 [%0], {%1,%2,%3,%4};" \
        :: "r"(a), "r"((v).x), "r"((v).y), "r"((v).z), "r"((v).w) : "memory")
#define CP16(sm, gp) \
    asm volatile("cp.async.cg.shared.global [%0], [%1], 16;" :: "r"(sm), "l"(gp) : "memory")
#define CP_COMMIT() asm volatile("cp.async.commit_group;" ::: "memory")
#define CP_WAIT(n)  asm volatile("cp.async.wait_group %0;" :: "n"(n) : "memory")

extern __shared__ __align__(16) char dsmem[];

// ===================== prep_w: transpose + split W once (coalesced) =========
__global__ __launch_bounds__(256) void prep_w(
    const float* __restrict__ WQ,
    const float* __restrict__ WK,
    const float* __restrict__ WV)
{
    __shared__ float sw[64][65];
    const int tid = threadIdx.x;
    const int m   = blockIdx.x / 6;
    const int kk  = (blockIdx.x % 6) * 64;
    const float* W = (m == 0) ? WQ : ((m == 1) ? WK : WV);

#pragma unroll
    for (int it = 0; it < 4; it++) {
        int idx = tid + (it << 8);
        int k = idx >> 4, n4 = (idx & 15) << 2;
        float4 v = *(const float4*)(W + (size_t)(kk + k) * DKn + n4);
        sw[k][n4] = v.x; sw[k][n4 + 1] = v.y; sw[k][n4 + 2] = v.z; sw[k][n4 + 3] = v.w;
    }
    __syncthreads();

#pragma unroll
    for (int it = 0; it < 2; it++) {
        int idx = tid + (it << 8);
        int n = idx >> 3, k0 = (idx & 7) << 3;
        uint32_t h[4], lo[4];
#pragma unroll
        for (int j = 0; j < 4; j++)
            split2(sw[k0 + 2 * j][n], sw[k0 + 2 * j + 1][n], h[j], lo[j]);
        size_t off = (size_t)(m * 64 + n) * Cn + kk + k0;
        *(uint4*)(g_wthi + off) = make_uint4(h[0], h[1], h[2], h[3]);
        *(uint4*)(g_wtlo + off) = make_uint4(lo[0], lo[1], lo[2], lo[3]);
    }
}

// ===================== projection: fully async staging (round-9 form) =======
#define P_X0 0u
#define P_XSTRIDE 36864u
#define P_WT0 73728u
#define P_WSTRIDE 49152u
#define PROJ_SMEM (172032u + 128u)

// Q pre-scale: 0.125 * log2(e)  (exp2-domain softmax downstream)
#define QSCALE 0.180336878f

__device__ __forceinline__ void stage_wt_async(uint32_t dst, int kk, int tid) {
#pragma unroll
    for (int i = 0; i < 6; i++) {
        int idx = tid + (i << 8);
        int n = idx >> 3, u = idx & 7;
        uint32_t sw = (uint32_t)n * 128u + (uint32_t)((u ^ (n & 7)) << 4);
        CP16(dst + sw,          g_wthi + n * Cn + kk + (u << 3));
        CP16(dst + 24576u + sw, g_wtlo + n * Cn + kk + (u << 3));
    }
}
__device__ __forceinline__ void stage_x_async(uint32_t dst, const float* xp, int tid) {
#pragma unroll
    for (int i = 0; i < 8; i++) {
        int idx = tid + (i << 8);
        int r = idx >> 4, u = idx & 15;
        CP16(dst + (uint32_t)r * 288u + (uint32_t)(u << 4),
             xp + (size_t)r * Cn + (u << 2));
    }
}

__global__ __launch_bounds__(256, 1) void proj_tc_kernel(const float* __restrict__ x)
{
    uint32_t raw = smem_u32(dsmem);
    uint32_t sb  = (raw + 127u) & ~127u;
    char*    bp  = dsmem + (sb - raw);
    float (*vt)[65] = (float(*)[65])(bp + P_WT0);

    const int tid = threadIdx.x;
    const int w   = tid >> 5;
    const int l   = tid & 31;
    const int r0  = blockIdx.x * 128;

    float acc[24][4];
#pragma unroll
    for (int i = 0; i < 24; i++)
#pragma unroll
        for (int j = 0; j < 4; j++) acc[i][j] = 0.f;

    const int brow = l & 7;
    const int bu   = l >> 3;
    const int ra   = (w << 4) + (l >> 2);

    stage_x_async(sb + P_X0, x + (size_t)r0 * Cn, tid);
    stage_wt_async(sb + P_WT0, 0, tid);
    CP_COMMIT();

    for (int c = 0; c < Cn / 64; c++) {
        if (c + 1 < Cn / 64) {
            stage_x_async(sb + P_X0 + (uint32_t)((c + 1) & 1) * P_XSTRIDE,
                          x + (size_t)r0 * Cn + (c + 1) * 64, tid);
            stage_wt_async(sb + P_WT0 + (uint32_t)((c + 1) & 1) * P_WSTRIDE,
                           (c + 1) * 64, tid);
            CP_COMMIT();
            CP_WAIT(1);
        } else {
            CP_WAIT(0);
        }
        __syncthreads();

        const char*    xb  = bp + P_X0 + (uint32_t)(c & 1) * P_XSTRIDE;
        const uint32_t wtb = sb + P_WT0 + (uint32_t)(c & 1) * P_WSTRIDE;

        uint32_t ah[4][4], al[4][4];
        {
            const char* rowa = xb + (uint32_t)ra * 288u;
            const char* rowb = rowa + 8u * 288u;
#pragma unroll
            for (int ks = 0; ks < 4; ks++) {
                int c0 = (ks << 6) + ((l & 3) << 3);
                float2 p0 = *(const float2*)(rowa + c0);
                float2 p1 = *(const float2*)(rowb + c0);
                float2 p2 = *(const float2*)(rowa + c0 + 32);
                float2 p3 = *(const float2*)(rowb + c0 + 32);
                split2(p0.x, p0.y, ah[ks][0], al[ks][0]);
                split2(p1.x, p1.y, ah[ks][1], al[ks][1]);
                split2(p2.x, p2.y, ah[ks][2], al[ks][2]);
                split2(p3.x, p3.y, ah[ks][3], al[ks][3]);
            }
        }
#pragma unroll
        for (int nt = 0; nt < 24; nt++) {
            int rowb = (nt << 3) + brow;
            uint32_t rb = wtb + (uint32_t)rowb * 128u;
            uint32_t s0 = (uint32_t)((bu       ^ (rowb & 7)) << 4);
            uint32_t s1 = (uint32_t)(((4 + bu) ^ (rowb & 7)) << 4);
            uint32_t bh[8], bl[8];
            ldsm4(bh,     rb + s0);
            ldsm4(bh + 4, rb + s1);
            ldsm4(bl,     rb + 24576u + s0);
            ldsm4(bl + 4, rb + 24576u + s1);
#pragma unroll
            for (int s = 0; s < 4; s++) {
                mma16816(acc[nt], ah[s], bh[2 * s], bh[2 * s + 1]);
                mma16816(acc[nt], ah[s], bl[2 * s], bl[2 * s + 1]);
                mma16816(acc[nt], al[s], bh[2 * s], bh[2 * s + 1]);
            }
        }
        __syncthreads();
    }

    // ---- epilogue: Q (xQSCALE) / K split-store; V staged for transpose ----
    const int rl = (w << 4) + (l >> 2);
    const int cc = (l & 3) << 1;
    const size_t row0 = (size_t)(r0 + rl);
#pragma unroll
    for (int nt = 0; nt < 8; nt++) {
        int cidx = (nt << 3) + cc;
        uint32_t h, lo;
        split2(acc[nt][0] * QSCALE, acc[nt][1] * QSCALE, h, lo);
        *(uint32_t*)(g_qhi + row0 * 64 + cidx) = h;
        *(uint32_t*)(g_qlo + row0 * 64 + cidx) = lo;
        split2(acc[nt][2] * QSCALE, acc[nt][3] * QSCALE, h, lo);
        *(uint32_t*)(g_qhi + (row0 + 8) * 64 + cidx) = h;
        *(uint32_t*)(g_qlo + (row0 + 8) * 64 + cidx) = lo;

        split2(acc[nt + 8][0], acc[nt + 8][1], h, lo);
        *(uint32_t*)(g_khi + row0 * 64 + cidx) = h;
        *(uint32_t*)(g_klo + row0 * 64 + cidx) = lo;
        split2(acc[nt + 8][2], acc[nt + 8][3], h, lo);
        *(uint32_t*)(g_khi + (row0 + 8) * 64 + cidx) = h;
        *(uint32_t*)(g_klo + (row0 + 8) * 64 + cidx) = lo;

        vt[rl][cidx]         = acc[nt + 16][0];
        vt[rl][cidx + 1]     = acc[nt + 16][1];
        vt[rl + 8][cidx]     = acc[nt + 16][2];
        vt[rl + 8][cidx + 1] = acc[nt + 16][3];
    }
    __syncthreads();

    {
        const int b  = r0 >> 11;
        const int t0 = r0 & 2047;
        const int d  = tid >> 2;
        const int tq = (tid & 3) << 5;
#pragma unroll
        for (int g = 0; g < 8; g++) {
            int tl = tq + g * 4;
            float v0 = vt[tl][d], v1 = vt[tl + 1][d];
            float v2 = vt[tl + 2][d], v3 = vt[tl + 3][d];
            uint32_t h0, h1, l0, l1;
            split2(v0, v1, h0, l0);
            split2(v2, v3, h1, l1);
            size_t off = ((size_t)(b * DKn + d) << 11) + t0 + tl;
            *(uint2*)(g_vthi + off) = make_uint2(h0, h1);
            *(uint2*)(g_vtlo + off) = make_uint2(l0, l1);
        }
    }
}

// ===================== attention: deferred-PV pipeline, triple buffer =======
// smem: 3 KV buffers @0, each 32KB: KHI +0, KLO +8192, VHI +16384, VLO +24576
#define A_KHI 0u
#define A_KLO 8192u
#define A_VHI 16384u
#define A_VLO 24576u
#define ATTN_SMEM (98304u + 128u)

__device__ __forceinline__ void stage_kv_async(uint32_t dst, int b, int ks, int tid) {
    const __nv_bfloat16* kh = g_khi + (((size_t)(b * Tn + ks)) << 6);
    const __nv_bfloat16* kl = g_klo + (((size_t)(b * Tn + ks)) << 6);
    const __nv_bfloat16* vh = g_vthi + (((size_t)(b * DKn)) << 11) + ks;
    const __nv_bfloat16* vl = g_vtlo + (((size_t)(b * DKn)) << 11) + ks;
#pragma unroll
    for (int i = 0; i < 4; i++) {
        int idx = tid + (i << 7);
        int r = idx >> 3, u = idx & 7;
        uint32_t sw = (uint32_t)r * 128u + (uint32_t)((u ^ (r & 7)) << 4);
        CP16(dst + A_KHI + sw, kh + (r << 6) + (u << 3));
        CP16(dst + A_KLO + sw, kl + (r << 6) + (u << 3));
        CP16(dst + A_VHI + sw, vh + ((size_t)r << 11) + (u << 3));
        CP16(dst + A_VLO + sw, vl + ((size_t)r << 11) + (u << 3));
    }
}

__global__ __launch_bounds__(128, 2) void attn_kernel(float* __restrict__ out)
{
    uint32_t raw = smem_u32(dsmem);
    uint32_t sb  = (raw + 127u) & ~127u;

    const int tid = threadIdx.x;
    const int w   = tid >> 5;
    const int l   = tid & 31;

    const int bx = blockIdx.x;
    const int qt = 31 - (bx >> 4);          // heavy q-tiles first
    const int b  = bx & 15;
    const int q0 = qt << 6;
    const int ntiles = qt + 1;

    // prefetch tile 0 (depth-1 pipeline)
    stage_kv_async(sb, b, 0, tid);
    CP_COMMIT();

    // ---- Q fragments directly from global (resident whole loop) ----
    uint32_t qh[4][4], qlr[4][4];
    {
        const int rowa = q0 + (w << 4) + (l >> 2);
        const int cb   = (l & 3) << 1;
        const __nv_bfloat16* ph = g_qhi + (((size_t)(b * Tn + rowa)) << 6) + cb;
        const __nv_bfloat16* pl = g_qlo + (((size_t)(b * Tn + rowa)) << 6) + cb;
#pragma unroll
        for (int ks = 0; ks < 4; ks++) {
            int c0 = ks << 4;
            qh[ks][0]  = *(const uint32_t*)(ph + c0);
            qh[ks][1]  = *(const uint32_t*)(ph + 512 + c0);
            qh[ks][2]  = *(const uint32_t*)(ph + c0 + 8);
            qh[ks][3]  = *(const uint32_t*)(ph + 512 + c0 + 8);
            qlr[ks][0] = *(const uint32_t*)(pl + c0);
            qlr[ks][1] = *(const uint32_t*)(pl + 512 + c0);
            qlr[ks][2] = *(const uint32_t*)(pl + c0 + 8);
            qlr[ks][3] = *(const uint32_t*)(pl + 512 + c0 + 8);
        }
    }

    float m0 = -3.0e38f, m1 = -3.0e38f, ls0 = 0.f, ls1 = 0.f;
    float o[8][4];
#pragma unroll
    for (int i = 0; i < 8; i++)
#pragma unroll
        for (int j = 0; j < 4; j++) o[i][j] = 0.f;

    // pending-PV pipeline state
    uint32_t phiP[4][4], ploP[4][4];
    float cP0 = 1.f, cP1 = 1.f;

    const int wrow0 = q0 + (w << 4);
    const int brow  = l & 7;
    const int bu    = l >> 3;

    for (int it = 0; it < ntiles; it++) {
        const int ks = it << 6;
        CP_WAIT(0);
        __syncthreads();
        if (it + 1 < ntiles) {
            stage_kv_async(sb + (uint32_t)((it + 1) % 3) * 32768u, b, ks + 64, tid);
            CP_COMMIT();
        }
        const uint32_t kvb = sb + (uint32_t)(it % 3) * 32768u;

        // ---- S = Q K^T (every warp active every tile in 64-row shape) ----
        float sc[8][4];
#pragma unroll
        for (int nt = 0; nt < 8; nt++) {
            int row = (nt << 3) + brow;
            uint32_t rb = kvb + (uint32_t)row * 128u;
            uint32_t s0 = (uint32_t)((bu       ^ (row & 7)) << 4);
            uint32_t s1 = (uint32_t)(((4 + bu) ^ (row & 7)) << 4);
            uint32_t kh8[8], kl8[8];
            ldsm4(kh8,     rb + A_KHI + s0);
            ldsm4(kh8 + 4, rb + A_KHI + s1);
            ldsm4(kl8,     rb + A_KLO + s0);
            ldsm4(kl8 + 4, rb + A_KLO + s1);
#pragma unroll
            for (int j = 0; j < 4; j++) sc[nt][j] = 0.f;
#pragma unroll
            for (int s = 0; s < 4; s++) {
                mma16816(sc[nt], qh[s],  kh8[2 * s], kh8[2 * s + 1]);
                mma16816(sc[nt], qh[s],  kl8[2 * s], kl8[2 * s + 1]);
                mma16816(sc[nt], qlr[s], kh8[2 * s], kh8[2 * s + 1]);
            }
        }

        // ---- causal mask (fires only on the diagonal tile) ----
        const int R0 = wrow0 + (l >> 2);
        if (ks + 64 > wrow0) {
            int colb = ks + ((l & 3) << 1);
#pragma unroll
            for (int nt = 0; nt < 8; nt++) {
                int c0 = colb + (nt << 3);
                if (c0     > R0)     sc[nt][0] = -3.0e38f;
                if (c0 + 1 > R0)     sc[nt][1] = -3.0e38f;
                if (c0     > R0 + 8) sc[nt][2] = -3.0e38f;
                if (c0 + 1 > R0 + 8) sc[nt][3] = -3.0e38f;
            }
        }

        // ---- max reduce (exp2 domain) ----
        float tm0 = -3.0e38f, tm1 = -3.0e38f;
#pragma unroll
        for (int nt = 0; nt < 8; nt++) {
            tm0 = fmaxf(tm0, fmaxf(sc[nt][0], sc[nt][1]));
            tm1 = fmaxf(tm1, fmaxf(sc[nt][2], sc[nt][3]));
        }
        tm0 = fmaxf(tm0, __shfl_xor_sync(0xffffffffu, tm0, 1));
        tm0 = fmaxf(tm0, __shfl_xor_sync(0xffffffffu, tm0, 2));
        tm1 = fmaxf(tm1, __shfl_xor_sync(0xffffffffu, tm1, 1));
        tm1 = fmaxf(tm1, __shfl_xor_sync(0xffffffffu, tm1, 2));
        float mn0 = fmaxf(m0, tm0), mn1 = fmaxf(m1, tm1);
        float c0 = ex2f(m0 - mn0), c1 = ex2f(m1 - mn1);

        // ---- pending PV from tile it-1 (tensor) — overlaps exp chain below ----
        if (it > 0) {
            const uint32_t vbs = sb + (uint32_t)((it - 1) % 3) * 32768u;
#pragma unroll
            for (int nt = 0; nt < 8; nt++) {
                o[nt][0] *= cP0; o[nt][1] *= cP0;
                o[nt][2] *= cP1; o[nt][3] *= cP1;
            }
#pragma unroll
            for (int nt = 0; nt < 8; nt++) {
                int row = (nt << 3) + brow;
                uint32_t rb = vbs + (uint32_t)row * 128u;
                uint32_t s0 = (uint32_t)((bu       ^ (row & 7)) << 4);
                uint32_t s1 = (uint32_t)(((4 + bu) ^ (row & 7)) << 4);
                uint32_t vh8[8], vl8[8];
                ldsm4(vh8,     rb + A_VHI + s0);
                ldsm4(vh8 + 4, rb + A_VHI + s1);
                ldsm4(vl8,     rb + A_VLO + s0);
                ldsm4(vl8 + 4, rb + A_VLO + s1);
#pragma unroll
                for (int s = 0; s < 4; s++) {
                    mma16816(o[nt], phiP[s], vh8[2 * s], vh8[2 * s + 1]);
                    mma16816(o[nt], phiP[s], vl8[2 * s], vl8[2 * s + 1]);
                    mma16816(o[nt], ploP[s], vh8[2 * s], vh8[2 * s + 1]);
                }
            }
        }

        // ---- exp chain (MUFU/FMA) — independent of PV above ----
        float ps0 = 0.f, ps1 = 0.f;
#pragma unroll
        for (int s = 0; s < 4; s++) {
#pragma unroll
            for (int h = 0; h < 2; h++) {
                int nt = 2 * s + h;
                float p0 = ex2f(sc[nt][0] - mn0);
                float p1 = ex2f(sc[nt][1] - mn0);
                float p2 = ex2f(sc[nt][2] - mn1);
                float p3 = ex2f(sc[nt][3] - mn1);
                ps0 += p0 + p1;
                ps1 += p2 + p3;
                split2(p0, p1, phiP[s][2 * h],     ploP[s][2 * h]);
                split2(p2, p3, phiP[s][2 * h + 1], ploP[s][2 * h + 1]);
            }
        }
        ps0 += __shfl_xor_sync(0xffffffffu, ps0, 1);
        ps0 += __shfl_xor_sync(0xffffffffu, ps0, 2);
        ps1 += __shfl_xor_sync(0xffffffffu, ps1, 1);
        ps1 += __shfl_xor_sync(0xffffffffu, ps1, 2);
        ls0 = ls0 * c0 + ps0;
        ls1 = ls1 * c1 + ps1;
        m0 = mn0; m1 = mn1;
        cP0 = c0; cP1 = c1;
    }

    // ---- flush pending PV of the last tile ----
    {
        const uint32_t vbs = sb + (uint32_t)((ntiles - 1) % 3) * 32768u;
#pragma unroll
        for (int nt = 0; nt < 8; nt++) {
            o[nt][0] *= cP0; o[nt][1] *= cP0;
            o[nt][2] *= cP1; o[nt][3] *= cP1;
        }
#pragma unroll
        for (int nt = 0; nt < 8; nt++) {
            int row = (nt << 3) + brow;
            uint32_t rb = vbs + (uint32_t)row * 128u;
            uint32_t s0 = (uint32_t)((bu       ^ (row & 7)) << 4);
            uint32_t s1 = (uint32_t)(((4 + bu) ^ (row & 7)) << 4);
            uint32_t vh8[8], vl8[8];
            ldsm4(vh8,     rb + A_VHI + s0);
            ldsm4(vh8 + 4, rb + A_VHI + s1);
            ldsm4(vl8,     rb + A_VLO + s0);
            ldsm4(vl8 + 4, rb + A_VLO + s1);
#pragma unroll
            for (int s = 0; s < 4; s++) {
                mma16816(o[nt], phiP[s], vh8[2 * s], vh8[2 * s + 1]);
                mma16816(o[nt], phiP[s], vl8[2 * s], vl8[2 * s + 1]);
                mma16816(o[nt], ploP[s], vh8[2 * s], vh8[2 * s + 1]);
            }
        }
    }

    const float inv0 = 1.f / ls0, inv1 = 1.f / ls1;
    const int R0g = q0 + (w << 4) + (l >> 2);
    float* o0p = out + (((size_t)(b * Tn + R0g)) << 6) + ((l & 3) << 1);
    float* o1p = o0p + (8 << 6);
#pragma unroll
    for (int nt = 0; nt < 8; nt++) {
        *(float2*)(o0p + (nt << 3)) = make_float2(o[nt][0] * inv0, o[nt][1] * inv0);
        *(float2*)(o1p + (nt << 3)) = make_float2(o[nt][2] * inv1, o[nt][3] * inv1);
    }
}

// ===================== launch =====================
extern "C" void kernel_launch(void* const* d_in, const int* in_sizes, int n_in,
                              void* d_out, int out_size)
{
    const float* x  = (const float*)d_in[0];
    const float* WQ = (const float*)d_in[1];
    const float* WK = (const float*)d_in[2];
    const float* WV = (const float*)d_in[3];
    float* out = (float*)d_out;

    cudaFuncSetAttribute(proj_tc_kernel,
                         cudaFuncAttributeMaxDynamicSharedMemorySize, PROJ_SMEM);
    cudaFuncSetAttribute(attn_kernel,
                         cudaFuncAttributeMaxDynamicSharedMemorySize, ATTN_SMEM);

    prep_w<<<18, 256>>>(WQ, WK, WV);
    proj_tc_kernel<<<256, 256, PROJ_SMEM>>>(x);
    attn_kernel<<<512, 128, ATTN_SMEM>>>(out);
}

// round 13
// speedup vs baseline: 1.4997x; 1.1878x over previous
#include <cuda_runtime.h>
#include <cuda_bf16.h>
#include <cuda_fp16.h>
#include <cstdint>

#define Bn  16
#define Tn  2048
#define Cn  384
#define DKn 64

// fp16 operands for attention (Q/P need hi only; K/V split hi+lo)
__device__ __align__(16) __half g_qh [Bn * Tn * DKn];
__device__ __align__(16) __half g_kh [Bn * Tn * DKn];
__device__ __align__(16) __half g_kl [Bn * Tn * DKn];
__device__ __align__(16) __half g_vth[Bn * DKn * Tn];   // [b][d][t]
__device__ __align__(16) __half g_vtl[Bn * DKn * Tn];
// Pre-transposed, pre-split bf16 weights for proj: [n][k], n 0..191 = [Q|K|V]
__device__ __align__(16) __nv_bfloat16 g_wthi[192 * Cn];
__device__ __align__(16) __nv_bfloat16 g_wtlo[192 * Cn];

// ===================== helpers =====================
__device__ __forceinline__ uint32_t smem_u32(const void* p) {
    uint32_t a;
    asm("{ .reg .u64 t; cvta.to.shared.u64 t, %1; cvt.u32.u64 %0, t; }" : "=r"(a) : "l"(p));
    return a;
}
// bf16 split (proj internals)
__device__ __forceinline__ uint32_t pack2(float e0, float e1) {
    uint32_t r;
    asm("cvt.rn.bf16x2.f32 %0, %1, %2;" : "=r"(r) : "f"(e1), "f"(e0));
    return r;
}
__device__ __forceinline__ void split2(float e0, float e1, uint32_t& hi, uint32_t& lo) {
    hi = pack2(e0, e1);
    float h0 = __uint_as_float(hi << 16);
    float h1 = __uint_as_float(hi & 0xffff0000u);
    lo = pack2(e0 - h0, e1 - h1);
}
// fp16 pack / split (attention operands)
__device__ __forceinline__ uint32_t packh2(float e0, float e1) {
    __half2 h = __floats2half2_rn(e0, e1);
    return *reinterpret_cast<uint32_t*>(&h);
}
__device__ __forceinline__ void split2h(float e0, float e1, uint32_t& hi, uint32_t& lo) {
    __half2 h = __floats2half2_rn(e0, e1);
    float2 hf = __half22float2(h);
    hi = *reinterpret_cast<uint32_t*>(&h);
    __half2 l = __floats2half2_rn(e0 - hf.x, e1 - hf.y);
    lo = *reinterpret_cast<uint32_t*>(&l);
}
__device__ __forceinline__ float ex2f(float x) {
    float r;
    asm("ex2.approx.f32 %0, %1;" : "=f"(r) : "f"(x));
    return r;
}
__device__ __forceinline__ void ldsm4(uint32_t r[4], uint32_t addr) {
    asm volatile("ldmatrix.sync.aligned.m8n8.x4.shared.b16 {%0,%1,%2,%3}, [%4];"
        : "=r"(r[0]), "=r"(r[1]), "=r"(r[2]), "=r"(r[3]) : "r"(addr));
}
__device__ __forceinline__ void mma16816(float c[4], const uint32_t a[4],
                                         uint32_t b0, uint32_t b1) {
    asm volatile(
        "mma.sync.aligned.m16n8k16.row.col.f32.bf16.bf16.f32 "
        "{%0,%1,%2,%3},{%4,%5,%6,%7},{%8,%9},{%0,%1,%2,%3};"
        : "+f"(c[0]), "+f"(c[1]), "+f"(c[2]), "+f"(c[3])
        : "r"(a[0]), "r"(a[1]), "r"(a[2]), "r"(a[3]), "r"(b0), "r"(b1));
}
__device__ __forceinline__ void mma16816h(float c[4], const uint32_t a[4],
                                          uint32_t b0, uint32_t b1) {
    asm volatile(
        "mma.sync.aligned.m16n8k16.row.col.f32.f16.f16.f32 "
        "{%0,%1,%2,%3},{%4,%5,%6,%7},{%8,%9},{%0,%1,%2,%3};"
        : "+f"(c[0]), "+f"(c[1]), "+f"(c[2]), "+f"(c[3])
        : "r"(a[0]), "r"(a[1]), "r"(a[2]), "r"(a[3]), "r"(b0), "r"(b1));
}
#define STS128(a, v) \
    asm volatile("st.shared.v4.b32 [%0], {%1,%2,%3,%4};" \
        :: "r"(a), "r"((v).x), "r"((v).y), "r"((v).z), "r"((v).w) : "memory")
#define CP16(sm, gp) \
    asm volatile("cp.async.cg.shared.global [%0], [%1], 16;" :: "r"(sm), "l"(gp) : "memory")
#define CP_COMMIT() asm volatile("cp.async.commit_group;" ::: "memory")
#define CP_WAIT(n)  asm volatile("cp.async.wait_group %0;" :: "n"(n) : "memory")

extern __shared__ __align__(16) char dsmem[];

// ===================== prep_w: transpose + split W once (bf16, coalesced) ===
__global__ __launch_bounds__(256) void prep_w(
    const float* __restrict__ WQ,
    const float* __restrict__ WK,
    const float* __restrict__ WV)
{
    __shared__ float sw[64][65];
    const int tid = threadIdx.x;
    const int m   = blockIdx.x / 6;
    const int kk  = (blockIdx.x % 6) * 64;
    const float* W = (m == 0) ? WQ : ((m == 1) ? WK : WV);

#pragma unroll
    for (int it = 0; it < 4; it++) {
        int idx = tid + (it << 8);
        int k = idx >> 4, n4 = (idx & 15) << 2;
        float4 v = *(const float4*)(W + (size_t)(kk + k) * DKn + n4);
        sw[k][n4] = v.x; sw[k][n4 + 1] = v.y; sw[k][n4 + 2] = v.z; sw[k][n4 + 3] = v.w;
    }
    __syncthreads();

#pragma unroll
    for (int it = 0; it < 2; it++) {
        int idx = tid + (it << 8);
        int n = idx >> 3, k0 = (idx & 7) << 3;
        uint32_t h[4], lo[4];
#pragma unroll
        for (int j = 0; j < 4; j++)
            split2(sw[k0 + 2 * j][n], sw[k0 + 2 * j + 1][n], h[j], lo[j]);
        size_t off = (size_t)(m * 64 + n) * Cn + kk + k0;
        *(uint4*)(g_wthi + off) = make_uint4(h[0], h[1], h[2], h[3]);
        *(uint4*)(g_wtlo + off) = make_uint4(lo[0], lo[1], lo[2], lo[3]);
    }
}

// ===================== projection: bf16 3-term, async staging ===============
#define P_X0 0u
#define P_XSTRIDE 36864u
#define P_WT0 73728u
#define P_WSTRIDE 49152u
#define PROJ_SMEM (172032u + 128u)

// Q pre-scale: 0.125 * log2(e)  (exp2-domain softmax downstream)
#define QSCALE 0.180336878f

__device__ __forceinline__ void stage_wt_async(uint32_t dst, int kk, int tid) {
#pragma unroll
    for (int i = 0; i < 6; i++) {
        int idx = tid + (i << 8);
        int n = idx >> 3, u = idx & 7;
        uint32_t sw = (uint32_t)n * 128u + (uint32_t)((u ^ (n & 7)) << 4);
        CP16(dst + sw,          g_wthi + n * Cn + kk + (u << 3));
        CP16(dst + 24576u + sw, g_wtlo + n * Cn + kk + (u << 3));
    }
}
__device__ __forceinline__ void stage_x_async(uint32_t dst, const float* xp, int tid) {
#pragma unroll
    for (int i = 0; i < 8; i++) {
        int idx = tid + (i << 8);
        int r = idx >> 4, u = idx & 15;
        CP16(dst + (uint32_t)r * 288u + (uint32_t)(u << 4),
             xp + (size_t)r * Cn + (u << 2));
    }
}

__global__ __launch_bounds__(256, 1) void proj_tc_kernel(const float* __restrict__ x)
{
    uint32_t raw = smem_u32(dsmem);
    uint32_t sb  = (raw + 127u) & ~127u;
    char*    bp  = dsmem + (sb - raw);
    float (*vt)[65] = (float(*)[65])(bp + P_WT0);

    const int tid = threadIdx.x;
    const int w   = tid >> 5;
    const int l   = tid & 31;
    const int r0  = blockIdx.x * 128;

    float acc[24][4];
#pragma unroll
    for (int i = 0; i < 24; i++)
#pragma unroll
        for (int j = 0; j < 4; j++) acc[i][j] = 0.f;

    const int brow = l & 7;
    const int bu   = l >> 3;
    const int ra   = (w << 4) + (l >> 2);

    stage_x_async(sb + P_X0, x + (size_t)r0 * Cn, tid);
    stage_wt_async(sb + P_WT0, 0, tid);
    CP_COMMIT();

    for (int c = 0; c < Cn / 64; c++) {
        if (c + 1 < Cn / 64) {
            stage_x_async(sb + P_X0 + (uint32_t)((c + 1) & 1) * P_XSTRIDE,
                          x + (size_t)r0 * Cn + (c + 1) * 64, tid);
            stage_wt_async(sb + P_WT0 + (uint32_t)((c + 1) & 1) * P_WSTRIDE,
                           (c + 1) * 64, tid);
            CP_COMMIT();
            CP_WAIT(1);
        } else {
            CP_WAIT(0);
        }
        __syncthreads();

        const char*    xb  = bp + P_X0 + (uint32_t)(c & 1) * P_XSTRIDE;
        const uint32_t wtb = sb + P_WT0 + (uint32_t)(c & 1) * P_WSTRIDE;

        uint32_t ah[4][4], al[4][4];
        {
            const char* rowa = xb + (uint32_t)ra * 288u;
            const char* rowb = rowa + 8u * 288u;
#pragma unroll
            for (int ks = 0; ks < 4; ks++) {
                int c0 = (ks << 6) + ((l & 3) << 3);
                float2 p0 = *(const float2*)(rowa + c0);
                float2 p1 = *(const float2*)(rowb + c0);
                float2 p2 = *(const float2*)(rowa + c0 + 32);
                float2 p3 = *(const float2*)(rowb + c0 + 32);
                split2(p0.x, p0.y, ah[ks][0], al[ks][0]);
                split2(p1.x, p1.y, ah[ks][1], al[ks][1]);
                split2(p2.x, p2.y, ah[ks][2], al[ks][2]);
                split2(p3.x, p3.y, ah[ks][3], al[ks][3]);
            }
        }
#pragma unroll
        for (int nt = 0; nt < 24; nt++) {
            int rowb = (nt << 3) + brow;
            uint32_t rb = wtb + (uint32_t)rowb * 128u;
            uint32_t s0 = (uint32_t)((bu       ^ (rowb & 7)) << 4);
            uint32_t s1 = (uint32_t)(((4 + bu) ^ (rowb & 7)) << 4);
            uint32_t bh[8], bl[8];
            ldsm4(bh,     rb + s0);
            ldsm4(bh + 4, rb + s1);
            ldsm4(bl,     rb + 24576u + s0);
            ldsm4(bl + 4, rb + 24576u + s1);
#pragma unroll
            for (int s = 0; s < 4; s++) {
                mma16816(acc[nt], ah[s], bh[2 * s], bh[2 * s + 1]);
                mma16816(acc[nt], ah[s], bl[2 * s], bl[2 * s + 1]);
                mma16816(acc[nt], al[s], bh[2 * s], bh[2 * s + 1]);
            }
        }
        __syncthreads();
    }

    // ---- epilogue: Q (xQSCALE) hi-only; K split fp16; V staged ----
    const int rl = (w << 4) + (l >> 2);
    const int cc = (l & 3) << 1;
    const size_t row0 = (size_t)(r0 + rl);
#pragma unroll
    for (int nt = 0; nt < 8; nt++) {
        int cidx = (nt << 3) + cc;
        uint32_t h, lo;
        *(uint32_t*)(g_qh + row0 * 64 + cidx) =
            packh2(acc[nt][0] * QSCALE, acc[nt][1] * QSCALE);
        *(uint32_t*)(g_qh + (row0 + 8) * 64 + cidx) =
            packh2(acc[nt][2] * QSCALE, acc[nt][3] * QSCALE);

        split2h(acc[nt + 8][0], acc[nt + 8][1], h, lo);
        *(uint32_t*)(g_kh + row0 * 64 + cidx) = h;
        *(uint32_t*)(g_kl + row0 * 64 + cidx) = lo;
        split2h(acc[nt + 8][2], acc[nt + 8][3], h, lo);
        *(uint32_t*)(g_kh + (row0 + 8) * 64 + cidx) = h;
        *(uint32_t*)(g_kl + (row0 + 8) * 64 + cidx) = lo;

        vt[rl][cidx]         = acc[nt + 16][0];
        vt[rl][cidx + 1]     = acc[nt + 16][1];
        vt[rl + 8][cidx]     = acc[nt + 16][2];
        vt[rl + 8][cidx + 1] = acc[nt + 16][3];
    }
    __syncthreads();

    {
        const int b  = r0 >> 11;
        const int t0 = r0 & 2047;
        const int d  = tid >> 2;
        const int tq = (tid & 3) << 5;
#pragma unroll
        for (int g = 0; g < 8; g++) {
            int tl = tq + g * 4;
            float v0 = vt[tl][d], v1 = vt[tl + 1][d];
            float v2 = vt[tl + 2][d], v3 = vt[tl + 3][d];
            uint32_t h0, h1, l0, l1;
            split2h(v0, v1, h0, l0);
            split2h(v2, v3, h1, l1);
            size_t off = ((size_t)(b * DKn + d) << 11) + t0 + tl;
            *(uint2*)(g_vth + off) = make_uint2(h0, h1);
            *(uint2*)(g_vtl + off) = make_uint2(l0, l1);
        }
    }
}

// ===================== attention: fp16 2-product, triple buffer =============
// smem: 3 KV buffers @0, each 32KB: KHI +0, KLO +8192, VHI +16384, VLO +24576
#define A_KHI 0u
#define A_KLO 8192u
#define A_VHI 16384u
#define A_VLO 24576u
#define ATTN_SMEM (98304u + 128u)

__device__ __forceinline__ void stage_kv_async(uint32_t dst, int b, int ks, int tid) {
    const __half* kh = g_kh + (((size_t)(b * Tn + ks)) << 6);
    const __half* kl = g_kl + (((size_t)(b * Tn + ks)) << 6);
    const __half* vh = g_vth + (((size_t)(b * DKn)) << 11) + ks;
    const __half* vl = g_vtl + (((size_t)(b * DKn)) << 11) + ks;
#pragma unroll
    for (int i = 0; i < 4; i++) {
        int idx = tid + (i << 7);
        int r = idx >> 3, u = idx & 7;
        uint32_t sw = (uint32_t)r * 128u + (uint32_t)((u ^ (r & 7)) << 4);
        CP16(dst + A_KHI + sw, kh + (r << 6) + (u << 3));
        CP16(dst + A_KLO + sw, kl + (r << 6) + (u << 3));
        CP16(dst + A_VHI + sw, vh + ((size_t)r << 11) + (u << 3));
        CP16(dst + A_VLO + sw, vl + ((size_t)r << 11) + (u << 3));
    }
}

__global__ __launch_bounds__(128, 2) void attn_kernel(float* __restrict__ out)
{
    uint32_t raw = smem_u32(dsmem);
    uint32_t sb  = (raw + 127u) & ~127u;

    const int tid = threadIdx.x;
    const int w   = tid >> 5;
    const int l   = tid & 31;

    const int bx = blockIdx.x;
    const int qt = 31 - (bx >> 4);          // heavy q-tiles first
    const int b  = bx & 15;
    const int q0 = qt << 6;
    const int ntiles = qt + 1;

    // prefetch first two K/V tiles
    stage_kv_async(sb, b, 0, tid);
    CP_COMMIT();
    if (ntiles > 1) {
        stage_kv_async(sb + 32768u, b, 64, tid);
        CP_COMMIT();
    }

    // ---- Q hi fragments directly from global ----
    uint32_t qh[4][4];
    {
        const int rowa = q0 + (w << 4) + (l >> 2);
        const int cb   = (l & 3) << 1;
        const __half* ph = g_qh + (((size_t)(b * Tn + rowa)) << 6) + cb;
#pragma unroll
        for (int ks = 0; ks < 4; ks++) {
            int c0 = ks << 4;
            qh[ks][0] = *(const uint32_t*)(ph + c0);
            qh[ks][1] = *(const uint32_t*)(ph + 512 + c0);
            qh[ks][2] = *(const uint32_t*)(ph + c0 + 8);
            qh[ks][3] = *(const uint32_t*)(ph + 512 + c0 + 8);
        }
    }

    float m0 = -3.0e38f, m1 = -3.0e38f, ls0 = 0.f, ls1 = 0.f;
    float o[8][4];
#pragma unroll
    for (int i = 0; i < 8; i++)
#pragma unroll
        for (int j = 0; j < 4; j++) o[i][j] = 0.f;

    const int wrow0 = q0 + (w << 4);
    const int brow  = l & 7;
    const int bu    = l >> 3;

    int cslot = 0, pslot = 2;               // it%3 and (it+2)%3
    for (int it = 0; it < ntiles; it++) {
        const int ks = it << 6;
        if (it + 1 < ntiles) { CP_WAIT(1); } else { CP_WAIT(0); }
        __syncthreads();
        if (it + 2 < ntiles) {
            stage_kv_async(sb + (uint32_t)pslot * 32768u, b, ks + 128, tid);
            CP_COMMIT();
        }
        const uint32_t kvb = sb + (uint32_t)cslot * 32768u;
        cslot = (cslot == 2) ? 0 : cslot + 1;
        pslot = (pslot == 2) ? 0 : pslot + 1;

        // ---- S = Q K^T : qh*kh + qh*kl ----
        float sc[8][4];
#pragma unroll
        for (int nt = 0; nt < 8; nt++) {
            int row = (nt << 3) + brow;
            uint32_t rb = kvb + (uint32_t)row * 128u;
            uint32_t s0 = (uint32_t)((bu       ^ (row & 7)) << 4);
            uint32_t s1 = (uint32_t)(((4 + bu) ^ (row & 7)) << 4);
            uint32_t kh8[8], kl8[8];
            ldsm4(kh8,     rb + A_KHI + s0);
            ldsm4(kh8 + 4, rb + A_KHI + s1);
            ldsm4(kl8,     rb + A_KLO + s0);
            ldsm4(kl8 + 4, rb + A_KLO + s1);
#pragma unroll
            for (int j = 0; j < 4; j++) sc[nt][j] = 0.f;
#pragma unroll
            for (int s = 0; s < 4; s++) {
                mma16816h(sc[nt], qh[s], kh8[2 * s], kh8[2 * s + 1]);
                mma16816h(sc[nt], qh[s], kl8[2 * s], kl8[2 * s + 1]);
            }
        }

        // ---- causal mask (diagonal tile only) ----
        const int R0 = wrow0 + (l >> 2);
        if (ks + 64 > wrow0) {
            int colb = ks + ((l & 3) << 1);
#pragma unroll
            for (int nt = 0; nt < 8; nt++) {
                int c0 = colb + (nt << 3);
                if (c0     > R0)     sc[nt][0] = -3.0e38f;
                if (c0 + 1 > R0)     sc[nt][1] = -3.0e38f;
                if (c0     > R0 + 8) sc[nt][2] = -3.0e38f;
                if (c0 + 1 > R0 + 8) sc[nt][3] = -3.0e38f;
            }
        }

        // ---- online softmax (exp2 domain) ----
        float tm0 = -3.0e38f, tm1 = -3.0e38f;
#pragma unroll
        for (int nt = 0; nt < 8; nt++) {
            tm0 = fmaxf(tm0, fmaxf(sc[nt][0], sc[nt][1]));
            tm1 = fmaxf(tm1, fmaxf(sc[nt][2], sc[nt][3]));
        }
        tm0 = fmaxf(tm0, __shfl_xor_sync(0xffffffffu, tm0, 1));
        tm0 = fmaxf(tm0, __shfl_xor_sync(0xffffffffu, tm0, 2));
        tm1 = fmaxf(tm1, __shfl_xor_sync(0xffffffffu, tm1, 1));
        tm1 = fmaxf(tm1, __shfl_xor_sync(0xffffffffu, tm1, 2));
        float mn0 = fmaxf(m0, tm0), mn1 = fmaxf(m1, tm1);
        float c0 = ex2f(m0 - mn0), c1 = ex2f(m1 - mn1);

        float ps0 = 0.f, ps1 = 0.f;
        uint32_t phi[4][4];
#pragma unroll
        for (int s = 0; s < 4; s++) {
#pragma unroll
            for (int h = 0; h < 2; h++) {
                int nt = 2 * s + h;
                float p0 = ex2f(sc[nt][0] - mn0);
                float p1 = ex2f(sc[nt][1] - mn0);
                float p2 = ex2f(sc[nt][2] - mn1);
                float p3 = ex2f(sc[nt][3] - mn1);
                ps0 += p0 + p1;
                ps1 += p2 + p3;
                phi[s][2 * h]     = packh2(p0, p1);
                phi[s][2 * h + 1] = packh2(p2, p3);
            }
        }
        ps0 += __shfl_xor_sync(0xffffffffu, ps0, 1);
        ps0 += __shfl_xor_sync(0xffffffffu, ps0, 2);
        ps1 += __shfl_xor_sync(0xffffffffu, ps1, 1);
        ps1 += __shfl_xor_sync(0xffffffffu, ps1, 2);
        ls0 = ls0 * c0 + ps0;
        ls1 = ls1 * c1 + ps1;
        m0 = mn0; m1 = mn1;

        // ---- O = O*c + P V : ph*vh + ph*vl ----
#pragma unroll
        for (int nt = 0; nt < 8; nt++) {
            o[nt][0] *= c0; o[nt][1] *= c0;
            o[nt][2] *= c1; o[nt][3] *= c1;
        }
#pragma unroll
        for (int nt = 0; nt < 8; nt++) {
            int row = (nt << 3) + brow;
            uint32_t rb = kvb + (uint32_t)row * 128u;
            uint32_t s0 = (uint32_t)((bu       ^ (row & 7)) << 4);
            uint32_t s1 = (uint32_t)(((4 + bu) ^ (row & 7)) << 4);
            uint32_t vh8[8], vl8[8];
            ldsm4(vh8,     rb + A_VHI + s0);
            ldsm4(vh8 + 4, rb + A_VHI + s1);
            ldsm4(vl8,     rb + A_VLO + s0);
            ldsm4(vl8 + 4, rb + A_VLO + s1);
#pragma unroll
            for (int s = 0; s < 4; s++) {
                mma16816h(o[nt], phi[s], vh8[2 * s], vh8[2 * s + 1]);
                mma16816h(o[nt], phi[s], vl8[2 * s], vl8[2 * s + 1]);
            }
        }
    }

    const float inv0 = 1.f / ls0, inv1 = 1.f / ls1;
    const int R0g = q0 + (w << 4) + (l >> 2);
    float* o0p = out + (((size_t)(b * Tn + R0g)) << 6) + ((l & 3) << 1);
    float* o1p = o0p + (8 << 6);
#pragma unroll
    for (int nt = 0; nt < 8; nt++) {
        *(float2*)(o0p + (nt << 3)) = make_float2(o[nt][0] * inv0, o[nt][1] * inv0);
        *(float2*)(o1p + (nt << 3)) = make_float2(o[nt][2] * inv1, o[nt][3] * inv1);
    }
}

// ===================== launch =====================
extern "C" void kernel_launch(void* const* d_in, const int* in_sizes, int n_in,
                              void* d_out, int out_size)
{
    const float* x  = (const float*)d_in[0];
    const float* WQ = (const float*)d_in[1];
    const float* WK = (const float*)d_in[2];
    const float* WV = (const float*)d_in[3];
    float* out = (float*)d_out;

    cudaFuncSetAttribute(proj_tc_kernel,
                         cudaFuncAttributeMaxDynamicSharedMemorySize, PROJ_SMEM);
    cudaFuncSetAttribute(attn_kernel,
                         cudaFuncAttributeMaxDynamicSharedMemorySize, ATTN_SMEM);

    prep_w<<<18, 256>>>(WQ, WK, WV);
    proj_tc_kernel<<<256, 256, PROJ_SMEM>>>(x);
    attn_kernel<<<512, 128, ATTN_SMEM>>>(out);
}

// round 14
// speedup vs baseline: 1.5559x; 1.0374x over previous
#include <cuda_runtime.h>
#include <cuda_bf16.h>
#include <cuda_fp16.h>
#include <cstdint>

#define Bn  16
#define Tn  2048
#define Cn  384
#define DKn 64

// fp16 operands for attention (Q/P need hi only; K/V split hi+lo)
__device__ __align__(16) __half g_qh [Bn * Tn * DKn];
__device__ __align__(16) __half g_kh [Bn * Tn * DKn];
__device__ __align__(16) __half g_kl [Bn * Tn * DKn];
__device__ __align__(16) __half g_vth[Bn * DKn * Tn];   // [b][d][t]
__device__ __align__(16) __half g_vtl[Bn * DKn * Tn];
// Pre-transposed, pre-split fp16 weights for proj: [n][k], n 0..191 = [Q|K|V]
__device__ __align__(16) __half g_wth[192 * Cn];
__device__ __align__(16) __half g_wtl[192 * Cn];

// ===================== helpers =====================
__device__ __forceinline__ uint32_t smem_u32(const void* p) {
    uint32_t a;
    asm("{ .reg .u64 t; cvta.to.shared.u64 t, %1; cvt.u32.u64 %0, t; }" : "=r"(a) : "l"(p));
    return a;
}
// fp16 pack / split
__device__ __forceinline__ uint32_t packh2(float e0, float e1) {
    __half2 h = __floats2half2_rn(e0, e1);
    return *reinterpret_cast<uint32_t*>(&h);
}
__device__ __forceinline__ void split2h(float e0, float e1, uint32_t& hi, uint32_t& lo) {
    __half2 h = __floats2half2_rn(e0, e1);
    float2 hf = __half22float2(h);
    hi = *reinterpret_cast<uint32_t*>(&h);
    __half2 l = __floats2half2_rn(e0 - hf.x, e1 - hf.y);
    lo = *reinterpret_cast<uint32_t*>(&l);
}
__device__ __forceinline__ float ex2f(float x) {
    float r;
    asm("ex2.approx.f32 %0, %1;" : "=f"(r) : "f"(x));
    return r;
}
__device__ __forceinline__ void ldsm4(uint32_t r[4], uint32_t addr) {
    asm volatile("ldmatrix.sync.aligned.m8n8.x4.shared.b16 {%0,%1,%2,%3}, [%4];"
        : "=r"(r[0]), "=r"(r[1]), "=r"(r[2]), "=r"(r[3]) : "r"(addr));
}
__device__ __forceinline__ void mma16816h(float c[4], const uint32_t a[4],
                                          uint32_t b0, uint32_t b1) {
    asm volatile(
        "mma.sync.aligned.m16n8k16.row.col.f32.f16.f16.f32 "
        "{%0,%1,%2,%3},{%4,%5,%6,%7},{%8,%9},{%0,%1,%2,%3};"
        : "+f"(c[0]), "+f"(c[1]), "+f"(c[2]), "+f"(c[3])
        : "r"(a[0]), "r"(a[1]), "r"(a[2]), "r"(a[3]), "r"(b0), "r"(b1));
}
#define STS128(a, v) \
    asm volatile("st.shared.v4.b32 [%0], {%1,%2,%3,%4};" \
        :: "r"(a), "r"((v).x), "r"((v).y), "r"((v).z), "r"((v).w) : "memory")
#define CP16(sm, gp) \
    asm volatile("cp.async.cg.shared.global [%0], [%1], 16;" :: "r"(sm), "l"(gp) : "memory")
#define CP_COMMIT() asm volatile("cp.async.commit_group;" ::: "memory")
#define CP_WAIT(n)  asm volatile("cp.async.wait_group %0;" :: "n"(n) : "memory")

extern __shared__ __align__(16) char dsmem[];

// ===================== prep_w: transpose + split W once (fp16, coalesced) ===
__global__ __launch_bounds__(256) void prep_w(
    const float* __restrict__ WQ,
    const float* __restrict__ WK,
    const float* __restrict__ WV)
{
    __shared__ float sw[64][65];
    const int tid = threadIdx.x;
    const int m   = blockIdx.x / 6;
    const int kk  = (blockIdx.x % 6) * 64;
    const float* W = (m == 0) ? WQ : ((m == 1) ? WK : WV);

#pragma unroll
    for (int it = 0; it < 4; it++) {
        int idx = tid + (it << 8);
        int k = idx >> 4, n4 = (idx & 15) << 2;
        float4 v = *(const float4*)(W + (size_t)(kk + k) * DKn + n4);
        sw[k][n4] = v.x; sw[k][n4 + 1] = v.y; sw[k][n4 + 2] = v.z; sw[k][n4 + 3] = v.w;
    }
    __syncthreads();

#pragma unroll
    for (int it = 0; it < 2; it++) {
        int idx = tid + (it << 8);
        int n = idx >> 3, k0 = (idx & 7) << 3;
        uint32_t h[4], lo[4];
#pragma unroll
        for (int j = 0; j < 4; j++)
            split2h(sw[k0 + 2 * j][n], sw[k0 + 2 * j + 1][n], h[j], lo[j]);
        size_t off = (size_t)(m * 64 + n) * Cn + kk + k0;
        *(uint4*)(g_wth + off) = make_uint4(h[0], h[1], h[2], h[3]);
        *(uint4*)(g_wtl + off) = make_uint4(lo[0], lo[1], lo[2], lo[3]);
    }
}

// ===================== projection: fp16 2-term, async staging ===============
#define P_X0 0u
#define P_XSTRIDE 36864u
#define P_WT0 73728u
#define P_WSTRIDE 49152u
#define PROJ_SMEM (172032u + 128u)

// Q pre-scale: 0.125 * log2(e)  (exp2-domain softmax downstream)
#define QSCALE 0.180336878f

__device__ __forceinline__ void stage_wt_async(uint32_t dst, int kk, int tid) {
#pragma unroll
    for (int i = 0; i < 6; i++) {
        int idx = tid + (i << 8);
        int n = idx >> 3, u = idx & 7;
        uint32_t sw = (uint32_t)n * 128u + (uint32_t)((u ^ (n & 7)) << 4);
        CP16(dst + sw,          g_wth + n * Cn + kk + (u << 3));
        CP16(dst + 24576u + sw, g_wtl + n * Cn + kk + (u << 3));
    }
}
__device__ __forceinline__ void stage_x_async(uint32_t dst, const float* xp, int tid) {
#pragma unroll
    for (int i = 0; i < 8; i++) {
        int idx = tid + (i << 8);
        int r = idx >> 4, u = idx & 15;
        CP16(dst + (uint32_t)r * 288u + (uint32_t)(u << 4),
             xp + (size_t)r * Cn + (u << 2));
    }
}

__global__ __launch_bounds__(256, 1) void proj_tc_kernel(const float* __restrict__ x)
{
    uint32_t raw = smem_u32(dsmem);
    uint32_t sb  = (raw + 127u) & ~127u;
    char*    bp  = dsmem + (sb - raw);
    float (*vt)[65] = (float(*)[65])(bp + P_WT0);

    const int tid = threadIdx.x;
    const int w   = tid >> 5;
    const int l   = tid & 31;
    const int r0  = blockIdx.x * 128;

    float acc[24][4];
#pragma unroll
    for (int i = 0; i < 24; i++)
#pragma unroll
        for (int j = 0; j < 4; j++) acc[i][j] = 0.f;

    const int brow = l & 7;
    const int bu   = l >> 3;
    const int ra   = (w << 4) + (l >> 2);

    stage_x_async(sb + P_X0, x + (size_t)r0 * Cn, tid);
    stage_wt_async(sb + P_WT0, 0, tid);
    CP_COMMIT();

    for (int c = 0; c < Cn / 64; c++) {
        if (c + 1 < Cn / 64) {
            stage_x_async(sb + P_X0 + (uint32_t)((c + 1) & 1) * P_XSTRIDE,
                          x + (size_t)r0 * Cn + (c + 1) * 64, tid);
            stage_wt_async(sb + P_WT0 + (uint32_t)((c + 1) & 1) * P_WSTRIDE,
                           (c + 1) * 64, tid);
            CP_COMMIT();
            CP_WAIT(1);
        } else {
            CP_WAIT(0);
        }
        __syncthreads();

        const char*    xb  = bp + P_X0 + (uint32_t)(c & 1) * P_XSTRIDE;
        const uint32_t wtb = sb + P_WT0 + (uint32_t)(c & 1) * P_WSTRIDE;

        // ---- A fragments: fp32 LDS -> fp16 pack (hi only, 2-term scheme) ----
        uint32_t ah[4][4];
        {
            const char* rowa = xb + (uint32_t)ra * 288u;
            const char* rowb = rowa + 8u * 288u;
#pragma unroll
            for (int ks = 0; ks < 4; ks++) {
                int c0 = (ks << 6) + ((l & 3) << 3);
                float2 p0 = *(const float2*)(rowa + c0);
                float2 p1 = *(const float2*)(rowb + c0);
                float2 p2 = *(const float2*)(rowa + c0 + 32);
                float2 p3 = *(const float2*)(rowb + c0 + 32);
                ah[ks][0] = packh2(p0.x, p0.y);
                ah[ks][1] = packh2(p1.x, p1.y);
                ah[ks][2] = packh2(p2.x, p2.y);
                ah[ks][3] = packh2(p3.x, p3.y);
            }
        }
#pragma unroll
        for (int nt = 0; nt < 24; nt++) {
            int rowb = (nt << 3) + brow;
            uint32_t rb = wtb + (uint32_t)rowb * 128u;
            uint32_t s0 = (uint32_t)((bu       ^ (rowb & 7)) << 4);
            uint32_t s1 = (uint32_t)(((4 + bu) ^ (rowb & 7)) << 4);
            uint32_t bh[8], bl[8];
            ldsm4(bh,     rb + s0);
            ldsm4(bh + 4, rb + s1);
            ldsm4(bl,     rb + 24576u + s0);
            ldsm4(bl + 4, rb + 24576u + s1);
#pragma unroll
            for (int s = 0; s < 4; s++) {
                mma16816h(acc[nt], ah[s], bh[2 * s], bh[2 * s + 1]);
                mma16816h(acc[nt], ah[s], bl[2 * s], bl[2 * s + 1]);
            }
        }
        __syncthreads();
    }

    // ---- epilogue: Q (xQSCALE) hi-only; K split fp16; V staged ----
    const int rl = (w << 4) + (l >> 2);
    const int cc = (l & 3) << 1;
    const size_t row0 = (size_t)(r0 + rl);
#pragma unroll
    for (int nt = 0; nt < 8; nt++) {
        int cidx = (nt << 3) + cc;
        uint32_t h, lo;
        *(uint32_t*)(g_qh + row0 * 64 + cidx) =
            packh2(acc[nt][0] * QSCALE, acc[nt][1] * QSCALE);
        *(uint32_t*)(g_qh + (row0 + 8) * 64 + cidx) =
            packh2(acc[nt][2] * QSCALE, acc[nt][3] * QSCALE);

        split2h(acc[nt + 8][0], acc[nt + 8][1], h, lo);
        *(uint32_t*)(g_kh + row0 * 64 + cidx) = h;
        *(uint32_t*)(g_kl + row0 * 64 + cidx) = lo;
        split2h(acc[nt + 8][2], acc[nt + 8][3], h, lo);
        *(uint32_t*)(g_kh + (row0 + 8) * 64 + cidx) = h;
        *(uint32_t*)(g_kl + (row0 + 8) * 64 + cidx) = lo;

        vt[rl][cidx]         = acc[nt + 16][0];
        vt[rl][cidx + 1]     = acc[nt + 16][1];
        vt[rl + 8][cidx]     = acc[nt + 16][2];
        vt[rl + 8][cidx + 1] = acc[nt + 16][3];
    }
    __syncthreads();

    {
        const int b  = r0 >> 11;
        const int t0 = r0 & 2047;
        const int d  = tid >> 2;
        const int tq = (tid & 3) << 5;
#pragma unroll
        for (int g = 0; g < 8; g++) {
            int tl = tq + g * 4;
            float v0 = vt[tl][d], v1 = vt[tl + 1][d];
            float v2 = vt[tl + 2][d], v3 = vt[tl + 3][d];
            uint32_t h0, h1, l0, l1;
            split2h(v0, v1, h0, l0);
            split2h(v2, v3, h1, l1);
            size_t off = ((size_t)(b * DKn + d) << 11) + t0 + tl;
            *(uint2*)(g_vth + off) = make_uint2(h0, h1);
            *(uint2*)(g_vtl + off) = make_uint2(l0, l1);
        }
    }
}

// ===================== attention: fp16 2-product, triple buffer =============
// smem: 3 KV buffers @0, each 32KB: KHI +0, KLO +8192, VHI +16384, VLO +24576
#define A_KHI 0u
#define A_KLO 8192u
#define A_VHI 16384u
#define A_VLO 24576u
#define ATTN_SMEM (98304u + 128u)

__device__ __forceinline__ void stage_kv_async(uint32_t dst, int b, int ks, int tid) {
    const __half* kh = g_kh + (((size_t)(b * Tn + ks)) << 6);
    const __half* kl = g_kl + (((size_t)(b * Tn + ks)) << 6);
    const __half* vh = g_vth + (((size_t)(b * DKn)) << 11) + ks;
    const __half* vl = g_vtl + (((size_t)(b * DKn)) << 11) + ks;
#pragma unroll
    for (int i = 0; i < 4; i++) {
        int idx = tid + (i << 7);
        int r = idx >> 3, u = idx & 7;
        uint32_t sw = (uint32_t)r * 128u + (uint32_t)((u ^ (r & 7)) << 4);
        CP16(dst + A_KHI + sw, kh + (r << 6) + (u << 3));
        CP16(dst + A_KLO + sw, kl + (r << 6) + (u << 3));
        CP16(dst + A_VHI + sw, vh + ((size_t)r << 11) + (u << 3));
        CP16(dst + A_VLO + sw, vl + ((size_t)r << 11) + (u << 3));
    }
}

__global__ __launch_bounds__(128, 2) void attn_kernel(float* __restrict__ out)
{
    uint32_t raw = smem_u32(dsmem);
    uint32_t sb  = (raw + 127u) & ~127u;

    const int tid = threadIdx.x;
    const int w   = tid >> 5;
    const int l   = tid & 31;

    const int bx = blockIdx.x;
    const int qt = 31 - (bx >> 4);          // heavy q-tiles first
    const int b  = bx & 15;
    const int q0 = qt << 6;
    const int ntiles = qt + 1;

    // prefetch first two K/V tiles
    stage_kv_async(sb, b, 0, tid);
    CP_COMMIT();
    if (ntiles > 1) {
        stage_kv_async(sb + 32768u, b, 64, tid);
        CP_COMMIT();
    }

    // ---- Q hi fragments directly from global ----
    uint32_t qh[4][4];
    {
        const int rowa = q0 + (w << 4) + (l >> 2);
        const int cb   = (l & 3) << 1;
        const __half* ph = g_qh + (((size_t)(b * Tn + rowa)) << 6) + cb;
#pragma unroll
        for (int ks = 0; ks < 4; ks++) {
            int c0 = ks << 4;
            qh[ks][0] = *(const uint32_t*)(ph + c0);
            qh[ks][1] = *(const uint32_t*)(ph + 512 + c0);
            qh[ks][2] = *(const uint32_t*)(ph + c0 + 8);
            qh[ks][3] = *(const uint32_t*)(ph + 512 + c0 + 8);
        }
    }

    float m0 = -3.0e38f, m1 = -3.0e38f, ls0 = 0.f, ls1 = 0.f;
    float o[8][4];
#pragma unroll
    for (int i = 0; i < 8; i++)
#pragma unroll
        for (int j = 0; j < 4; j++) o[i][j] = 0.f;

    const int wrow0 = q0 + (w << 4);
    const int brow  = l & 7;
    const int bu    = l >> 3;

    int cslot = 0, pslot = 2;               // it%3 and (it+2)%3
    for (int it = 0; it < ntiles; it++) {
        const int ks = it << 6;
        if (it + 1 < ntiles) { CP_WAIT(1); } else { CP_WAIT(0); }
        __syncthreads();
        if (it + 2 < ntiles) {
            stage_kv_async(sb + (uint32_t)pslot * 32768u, b, ks + 128, tid);
            CP_COMMIT();
        }
        const uint32_t kvb = sb + (uint32_t)cslot * 32768u;
        cslot = (cslot == 2) ? 0 : cslot + 1;
        pslot = (pslot == 2) ? 0 : pslot + 1;

        // ---- S = Q K^T : qh*kh + qh*kl ----
        float sc[8][4];
#pragma unroll
        for (int nt = 0; nt < 8; nt++) {
            int row = (nt << 3) + brow;
            uint32_t rb = kvb + (uint32_t)row * 128u;
            uint32_t s0 = (uint32_t)((bu       ^ (row & 7)) << 4);
            uint32_t s1 = (uint32_t)(((4 + bu) ^ (row & 7)) << 4);
            uint32_t kh8[8], kl8[8];
            ldsm4(kh8,     rb + A_KHI + s0);
            ldsm4(kh8 + 4, rb + A_KHI + s1);
            ldsm4(kl8,     rb + A_KLO + s0);
            ldsm4(kl8 + 4, rb + A_KLO + s1);
#pragma unroll
            for (int j = 0; j < 4; j++) sc[nt][j] = 0.f;
#pragma unroll
            for (int s = 0; s < 4; s++) {
                mma16816h(sc[nt], qh[s], kh8[2 * s], kh8[2 * s + 1]);
                mma16816h(sc[nt], qh[s], kl8[2 * s], kl8[2 * s + 1]);
            }
        }

        // ---- causal mask (diagonal tile only) ----
        const int R0 = wrow0 + (l >> 2);
        if (ks + 64 > wrow0) {
            int colb = ks + ((l & 3) << 1);
#pragma unroll
            for (int nt = 0; nt < 8; nt++) {
                int c0 = colb + (nt << 3);
                if (c0     > R0)     sc[nt][0] = -3.0e38f;
                if (c0 + 1 > R0)     sc[nt][1] = -3.0e38f;
                if (c0     > R0 + 8) sc[nt][2] = -3.0e38f;
                if (c0 + 1 > R0 + 8) sc[nt][3] = -3.0e38f;
            }
        }

        // ---- online softmax (exp2 domain) ----
        float tm0 = -3.0e38f, tm1 = -3.0e38f;
#pragma unroll
        for (int nt = 0; nt < 8; nt++) {
            tm0 = fmaxf(tm0, fmaxf(sc[nt][0], sc[nt][1]));
            tm1 = fmaxf(tm1, fmaxf(sc[nt][2], sc[nt][3]));
        }
        tm0 = fmaxf(tm0, __shfl_xor_sync(0xffffffffu, tm0, 1));
        tm0 = fmaxf(tm0, __shfl_xor_sync(0xffffffffu, tm0, 2));
        tm1 = fmaxf(tm1, __shfl_xor_sync(0xffffffffu, tm1, 1));
        tm1 = fmaxf(tm1, __shfl_xor_sync(0xffffffffu, tm1, 2));
        float mn0 = fmaxf(m0, tm0), mn1 = fmaxf(m1, tm1);
        float c0 = ex2f(m0 - mn0), c1 = ex2f(m1 - mn1);

        float ps0 = 0.f, ps1 = 0.f;
        uint32_t phi[4][4];
#pragma unroll
        for (int s = 0; s < 4; s++) {
#pragma unroll
            for (int h = 0; h < 2; h++) {
                int nt = 2 * s + h;
                float p0 = ex2f(sc[nt][0] - mn0);
                float p1 = ex2f(sc[nt][1] - mn0);
                float p2 = ex2f(sc[nt][2] - mn1);
                float p3 = ex2f(sc[nt][3] - mn1);
                ps0 += p0 + p1;
                ps1 += p2 + p3;
                phi[s][2 * h]     = packh2(p0, p1);
                phi[s][2 * h + 1] = packh2(p2, p3);
            }
        }
        ps0 += __shfl_xor_sync(0xffffffffu, ps0, 1);
        ps0 += __shfl_xor_sync(0xffffffffu, ps0, 2);
        ps1 += __shfl_xor_sync(0xffffffffu, ps1, 1);
        ps1 += __shfl_xor_sync(0xffffffffu, ps1, 2);
        ls0 = ls0 * c0 + ps0;
        ls1 = ls1 * c1 + ps1;
        m0 = mn0; m1 = mn1;

        // ---- O = O*c + P V : ph*vh + ph*vl ----
#pragma unroll
        for (int nt = 0; nt < 8; nt++) {
            o[nt][0] *= c0; o[nt][1] *= c0;
            o[nt][2] *= c1; o[nt][3] *= c1;
        }
#pragma unroll
        for (int nt = 0; nt < 8; nt++) {
            int row = (nt << 3) + brow;
            uint32_t rb = kvb + (uint32_t)row * 128u;
            uint32_t s0 = (uint32_t)((bu       ^ (row & 7)) << 4);
            uint32_t s1 = (uint32_t)(((4 + bu) ^ (row & 7)) << 4);
            uint32_t vh8[8], vl8[8];
            ldsm4(vh8,     rb + A_VHI + s0);
            ldsm4(vh8 + 4, rb + A_VHI + s1);
            ldsm4(vl8,     rb + A_VLO + s0);
            ldsm4(vl8 + 4, rb + A_VLO + s1);
#pragma unroll
            for (int s = 0; s < 4; s++) {
                mma16816h(o[nt], phi[s], vh8[2 * s], vh8[2 * s + 1]);
                mma16816h(o[nt], phi[s], vl8[2 * s], vl8[2 * s + 1]);
            }
        }
    }

    const float inv0 = 1.f / ls0, inv1 = 1.f / ls1;
    const int R0g = q0 + (w << 4) + (l >> 2);
    float* o0p = out + (((size_t)(b * Tn + R0g)) << 6) + ((l & 3) << 1);
    float* o1p = o0p + (8 << 6);
#pragma unroll
    for (int nt = 0; nt < 8; nt++) {
        *(float2*)(o0p + (nt << 3)) = make_float2(o[nt][0] * inv0, o[nt][1] * inv0);
        *(float2*)(o1p + (nt << 3)) = make_float2(o[nt][2] * inv1, o[nt][3] * inv1);
    }
}

// ===================== launch =====================
extern "C" void kernel_launch(void* const* d_in, const int* in_sizes, int n_in,
                              void* d_out, int out_size)
{
    const float* x  = (const float*)d_in[0];
    const float* WQ = (const float*)d_in[1];
    const float* WK = (const float*)d_in[2];
    const float* WV = (const float*)d_in[3];
    float* out = (float*)d_out;

    cudaFuncSetAttribute(proj_tc_kernel,
                         cudaFuncAttributeMaxDynamicSharedMemorySize, PROJ_SMEM);
    cudaFuncSetAttribute(attn_kernel,
                         cudaFuncAttributeMaxDynamicSharedMemorySize, ATTN_SMEM);

    prep_w<<<18, 256>>>(WQ, WK, WV);
    proj_tc_kernel<<<256, 256, PROJ_SMEM>>>(x);
    attn_kernel<<<512, 128, ATTN_SMEM>>>(out);
}